// round 1
// baseline (speedup 1.0000x reference)
#include <cuda_runtime.h>
#include <math.h>

#define B_SZ   16384
#define H_SZ   512
#define NODES  9
#define ROWS   (B_SZ * NODES)         // 147456
#define BH     (ROWS * H_SZ)          // 75497472 floats = 302 MB

// ---------------- scratch (device globals; no allocation) ----------------
__device__ float g_buf0[BH];
__device__ float g_buf1[BH];
__device__ float g_buf2[BH];
__device__ float g_buf3[BH];
__device__ float g_buf4[BH];
__device__ float g_wquat[H_SZ * H_SZ];
__device__ float g_wwav [H_SZ * H_SZ];

// ---------------- quaternion weight assembly ----------------
// out chunk co gets: sum_ci in_chunk_ci @ (sign * Wq_{which})
__constant__ int   c_which[16] = {0,1,2,3, 1,0,3,2, 2,3,0,1, 3,2,1,0};
__constant__ float c_sign [16] = {1.f,-1.f,-1.f,-1.f,
                                  1.f, 1.f, 1.f,-1.f,
                                  1.f,-1.f, 1.f, 1.f,
                                  1.f, 1.f,-1.f, 1.f};

__global__ void build_quat(const float* __restrict__ Wr, const float* __restrict__ Wi,
                           const float* __restrict__ Wj, const float* __restrict__ Wk,
                           float* __restrict__ Wq)
{
    int idx = blockIdx.x * 256 + threadIdx.x;       // 512*512 total
    int row = idx >> 9, col = idx & 511;
    int ci = row >> 7, hi = row & 127;
    int co = col >> 7, ho = col & 127;
    const float* mats[4] = {Wr, Wi, Wj, Wk};
    int sel = co * 4 + ci;
    Wq[idx] = c_sign[sel] * mats[c_which[sel]][hi * 128 + ho];
}

// wavelet: rec = m @ Wwav with interleave folded in
__global__ void build_wav(const float* __restrict__ Wl, const float* __restrict__ Wh,
                          float* __restrict__ Ww)
{
    int idx = blockIdx.x * 256 + threadIdx.x;       // 512*512 total
    int row = idx >> 9, col = idx & 511;
    int hi = row >> 1, pi = row & 1;
    int ho = col >> 1, po = col & 1;
    float wl = Wl[hi * 256 + ho];
    float wh = Wh[hi * 256 + ho];
    Ww[idx] = (pi == po) ? 0.5f * (wl + wh) : 0.5f * (wl - wh);
}

// ---------------- vortex aggregation: out[b,r] = 0.5*(in[b,r]+in[b,src(r)]), r=8 identity
__global__ void agg_k(const float* __restrict__ in, float* __restrict__ out)
{
    int idx = blockIdx.x * 256 + threadIdx.x;       // over B*9*128 float4
    const int TOT = B_SZ * NODES * (H_SZ / 4);
    if (idx >= TOT) return;
    int h4 = idx & 127;
    int rn = (idx >> 7) % NODES;
    int b  = idx / (NODES * 128);
    const float4* in4 = (const float4*)in;
    float4* out4 = (float4*)out;
    float4 a = in4[(b * NODES + rn) * 128 + h4];
    if (rn == 8) { out4[idx] = a; return; }
    int src = (rn & 1) ? (rn >> 1) : (rn >> 1) + 4;
    float4 c = in4[(b * NODES + src) * 128 + h4];
    out4[idx] = make_float4(0.5f*(a.x+c.x), 0.5f*(a.y+c.y), 0.5f*(a.z+c.z), 0.5f*(a.w+c.w));
}

// ---------------- SGEMM: C(MxN) = A(MxK, lda) @ B(KxN), row-major, fused epilogue
// EPI: 0 = none, 1 = bias+leakyrelu(0.01), 2 = bias+tanh, 3 = bias only
template<int EPI>
__global__ __launch_bounds__(256, 2)
void sgemm_k(const float* __restrict__ A, const float* __restrict__ B,
             const float* __restrict__ bias, float* __restrict__ C,
             int M, int N, int K, int lda)
{
    __shared__ float As[2][16][128];
    __shared__ float Bs[2][16][128];
    const int tid  = threadIdx.x;
    const int row0 = blockIdx.y * 128;
    const int col0 = blockIdx.x * 128;
    const int tx = tid & 15;
    const int ty = tid >> 4;
    const int ar = tid >> 2;            // 0..63
    const int ac = (tid & 3) << 2;      // 0,4,8,12
    const int br = tid >> 5;            // 0..7
    const int bc = (tid & 31) << 2;     // 0..124

    const float* Ag0 = A + (size_t)(row0 + ar) * lda + ac;
    const float* Ag1 = Ag0 + (size_t)64 * lda;
    const float* Bg0 = B + (size_t)br * N + col0 + bc;
    const float* Bg1 = Bg0 + (size_t)8 * N;

    float4 pa0 = *(const float4*)Ag0;
    float4 pa1 = *(const float4*)Ag1;
    float4 pb0 = *(const float4*)Bg0;
    float4 pb1 = *(const float4*)Bg1;

    As[0][ac+0][ar]    = pa0.x; As[0][ac+1][ar]    = pa0.y;
    As[0][ac+2][ar]    = pa0.z; As[0][ac+3][ar]    = pa0.w;
    As[0][ac+0][ar+64] = pa1.x; As[0][ac+1][ar+64] = pa1.y;
    As[0][ac+2][ar+64] = pa1.z; As[0][ac+3][ar+64] = pa1.w;
    *(float4*)&Bs[0][br  ][bc] = pb0;
    *(float4*)&Bs[0][br+8][bc] = pb1;
    __syncthreads();

    float acc[8][8];
    #pragma unroll
    for (int i = 0; i < 8; ++i)
        #pragma unroll
        for (int j = 0; j < 8; ++j) acc[i][j] = 0.f;

    const int nk = K >> 4;
    for (int t = 0; t < nk; ++t) {
        const int s = t & 1;
        if (t + 1 < nk) {
            pa0 = *(const float4*)(Ag0 + (t + 1) * 16);
            pa1 = *(const float4*)(Ag1 + (t + 1) * 16);
            pb0 = *(const float4*)(Bg0 + (size_t)(t + 1) * 16 * N);
            pb1 = *(const float4*)(Bg1 + (size_t)(t + 1) * 16 * N);
        }
        #pragma unroll
        for (int k = 0; k < 16; ++k) {
            float4 a0 = *(const float4*)&As[s][k][ty * 8];
            float4 a1 = *(const float4*)&As[s][k][ty * 8 + 4];
            float4 b0 = *(const float4*)&Bs[s][k][tx * 8];
            float4 b1 = *(const float4*)&Bs[s][k][tx * 8 + 4];
            float ra[8] = {a0.x,a0.y,a0.z,a0.w,a1.x,a1.y,a1.z,a1.w};
            float rb[8] = {b0.x,b0.y,b0.z,b0.w,b1.x,b1.y,b1.z,b1.w};
            #pragma unroll
            for (int i = 0; i < 8; ++i)
                #pragma unroll
                for (int j = 0; j < 8; ++j)
                    acc[i][j] = fmaf(ra[i], rb[j], acc[i][j]);
        }
        if (t + 1 < nk) {
            const int s2 = (t + 1) & 1;
            As[s2][ac+0][ar]    = pa0.x; As[s2][ac+1][ar]    = pa0.y;
            As[s2][ac+2][ar]    = pa0.z; As[s2][ac+3][ar]    = pa0.w;
            As[s2][ac+0][ar+64] = pa1.x; As[s2][ac+1][ar+64] = pa1.y;
            As[s2][ac+2][ar+64] = pa1.z; As[s2][ac+3][ar+64] = pa1.w;
            *(float4*)&Bs[s2][br  ][bc] = pb0;
            *(float4*)&Bs[s2][br+8][bc] = pb1;
            __syncthreads();
        }
    }

    #pragma unroll
    for (int i = 0; i < 8; ++i) {
        int r = row0 + ty * 8 + i;
        int c = col0 + tx * 8;
        float* Cp = C + (size_t)r * N + c;
        float o[8];
        #pragma unroll
        for (int j = 0; j < 8; ++j) {
            float v = acc[i][j];
            if (EPI != 0) {
                v += bias[c + j];
                if (EPI == 1)      v = v > 0.f ? v : 0.01f * v;
                else if (EPI == 2) v = tanhf(v);
            }
            o[j] = v;
        }
        *(float4*)(Cp)     = make_float4(o[0], o[1], o[2], o[3]);
        *(float4*)(Cp + 4) = make_float4(o[4], o[5], o[6], o[7]);
    }
}

// ---------------- fused attention core over 9 tokens: ctx written in place over Q
__global__ __launch_bounds__(256)
void attn_core(float* __restrict__ Q, const float* __restrict__ Kk,
               const float* __restrict__ Vv)
{
    __shared__ float sK[NODES * H_SZ];
    __shared__ float sV[NODES * H_SZ];
    __shared__ float sS[96];
    const int b   = blockIdx.x;
    const int tid = threadIdx.x;
    const size_t base = (size_t)b * NODES * H_SZ;

    const float4* K4 = (const float4*)(Kk + base);
    const float4* V4 = (const float4*)(Vv + base);
    for (int i = tid; i < NODES * H_SZ / 4; i += 256) {
        ((float4*)sK)[i] = K4[i];
        ((float4*)sV)[i] = V4[i];
    }
    __syncthreads();

    const float scale = 0.044194173824159216f;  // 1/sqrt(512)
    const int warp = tid >> 5, lane = tid & 31;
    for (int p = warp; p < 81; p += 8) {
        int q = p / 9, kk = p % 9;
        const float* Qr = Q + base + (size_t)q * H_SZ;
        float s = 0.f;
        #pragma unroll 4
        for (int h = lane; h < H_SZ; h += 32) s += Qr[h] * sK[kk * H_SZ + h];
        #pragma unroll
        for (int o = 16; o; o >>= 1) s += __shfl_down_sync(0xffffffffu, s, o);
        if (lane == 0) sS[q * 9 + kk] = s * scale;
    }
    __syncthreads();

    if (tid < 9) {
        float mx = -1e30f;
        #pragma unroll
        for (int k = 0; k < 9; ++k) mx = fmaxf(mx, sS[tid * 9 + k]);
        float sum = 0.f;
        #pragma unroll
        for (int k = 0; k < 9; ++k) { float e = expf(sS[tid * 9 + k] - mx); sS[tid * 9 + k] = e; sum += e; }
        float inv = 1.f / sum;
        #pragma unroll
        for (int k = 0; k < 9; ++k) sS[tid * 9 + k] *= inv;
    }
    __syncthreads();

    for (int q = 0; q < 9; ++q) {
        float a[9];
        #pragma unroll
        for (int k = 0; k < 9; ++k) a[k] = sS[q * 9 + k];
        for (int h = tid; h < H_SZ; h += 256) {
            float acc = 0.f;
            #pragma unroll
            for (int k = 0; k < 9; ++k) acc = fmaf(a[k], sV[k * H_SZ + h], acc);
            Q[base + (size_t)q * H_SZ + h] = acc;
        }
    }
}

// ---------------- drnorm + residual: NF = V + gamma*(A-mu)*rsqrt(var+eps) + beta
__global__ __launch_bounds__(256)
void drnorm_res(const float* __restrict__ A, const float* __restrict__ V,
                const float* __restrict__ gamma, const float* __restrict__ beta,
                float* __restrict__ NF)
{
    __shared__ float red[16];
    __shared__ float s_mu, s_inv;
    const int row = blockIdx.x;
    const int t = threadIdx.x;
    const size_t o0 = (size_t)row * H_SZ;
    float v1 = A[o0 + t], v2 = A[o0 + t + 256];
    float s = v1 + v2, sq = v1 * v1 + v2 * v2;
    #pragma unroll
    for (int o = 16; o; o >>= 1) {
        s  += __shfl_down_sync(0xffffffffu, s, o);
        sq += __shfl_down_sync(0xffffffffu, sq, o);
    }
    int warp = t >> 5, lane = t & 31;
    if (lane == 0) { red[warp] = s; red[warp + 8] = sq; }
    __syncthreads();
    if (t == 0) {
        float S = 0.f, SQ = 0.f;
        #pragma unroll
        for (int w = 0; w < 8; ++w) { S += red[w]; SQ += red[w + 8]; }
        float mu = S * (1.f / 512.f);
        float var = SQ * (1.f / 512.f) - mu * mu;
        s_mu = mu;
        s_inv = rsqrtf(var + 1e-5f);
    }
    __syncthreads();
    float mu = s_mu, inv = s_inv;
    NF[o0 + t]       = V[o0 + t]       + gamma[t]       * (v1 - mu) * inv + beta[t];
    NF[o0 + t + 256] = V[o0 + t + 256] + gamma[t + 256] * (v2 - mu) * inv + beta[t + 256];
}

// ---------------- host orchestration ----------------
static void run_attention(const float* Vin, float* NF,
                          const float* Wq, const float* Wk, const float* Wv, const float* Wo,
                          const float* gamma, const float* beta,
                          float* q, float* k, float* v)
{
    dim3 blk(256), gBig(4, ROWS / 128);
    sgemm_k<0><<<gBig, blk>>>(Vin, Wq, nullptr, q, ROWS, 512, 512, 512);
    sgemm_k<0><<<gBig, blk>>>(Vin, Wk, nullptr, k, ROWS, 512, 512, 512);
    sgemm_k<0><<<gBig, blk>>>(Vin, Wv, nullptr, v, ROWS, 512, 512, 512);
    attn_core<<<B_SZ, 256>>>(q, k, v);                       // ctx -> q (in place)
    sgemm_k<0><<<gBig, blk>>>(q, Wo, nullptr, k, ROWS, 512, 512, 512);  // A -> k
    drnorm_res<<<ROWS, 256>>>(k, Vin, gamma, beta, NF);
}

extern "C" void kernel_launch(void* const* d_in, const int* in_sizes, int n_in,
                              void* d_out, int out_size)
{
    const float* x      = (const float*)d_in[0];
    const float* W_in   = (const float*)d_in[1];
    const float* b_in   = (const float*)d_in[2];
    const float* W_dr   = (const float*)d_in[3];
    const float* b_dr   = (const float*)d_in[4];
    const float* W_hyp  = (const float*)d_in[5];
    const float* b_hyp  = (const float*)d_in[6];
    const float* Wq_r   = (const float*)d_in[7];
    const float* Wq_i   = (const float*)d_in[8];
    const float* Wq_j   = (const float*)d_in[9];
    const float* Wq_k   = (const float*)d_in[10];
    const float* b_quat = (const float*)d_in[11];
    const float* W_low  = (const float*)d_in[12];
    const float* W_high = (const float*)d_in[13];
    const float* b_wav  = (const float*)d_in[14];
    const float* aWq    = (const float*)d_in[15];
    const float* aWk    = (const float*)d_in[16];
    const float* aWv    = (const float*)d_in[17];
    const float* aWo    = (const float*)d_in[18];
    const float* gamma  = (const float*)d_in[19];
    const float* beta   = (const float*)d_in[20];
    const float* W_out  = (const float*)d_in[21];
    const float* b_out  = (const float*)d_in[22];
    float* out = (float*)d_out;

    float *buf0, *buf1, *buf2, *buf3, *buf4, *wq, *ww;
    cudaGetSymbolAddress((void**)&buf0, g_buf0);
    cudaGetSymbolAddress((void**)&buf1, g_buf1);
    cudaGetSymbolAddress((void**)&buf2, g_buf2);
    cudaGetSymbolAddress((void**)&buf3, g_buf3);
    cudaGetSymbolAddress((void**)&buf4, g_buf4);
    cudaGetSymbolAddress((void**)&wq,   g_wquat);
    cudaGetSymbolAddress((void**)&ww,   g_wwav);

    dim3 blk(256), gBig(4, ROWS / 128);
    const int AGG_BLOCKS = (B_SZ * NODES * (H_SZ / 4) + 255) / 256;

    // fold quaternion / wavelet layers into dense 512x512 weights
    build_quat<<<1024, 256>>>(Wq_r, Wq_i, Wq_j, Wq_k, wq);
    build_wav <<<1024, 256>>>(W_low, W_high, ww);

    // p = leakyrelu(x @ W_in + b_in)   -> buf0 (B x 4608) == (ROWS x 512)
    sgemm_k<1><<<dim3(36, 128), blk>>>(x, W_in, b_in, buf0, B_SZ, 9 * H_SZ, 512, 512);
    // nf = tanh(p @ W_dr + b_dr)       -> buf1
    sgemm_k<2><<<gBig, blk>>>(buf0, W_dr, b_dr, buf1, ROWS, 512, 512, 512);
    // m = agg(nf)                      -> buf2
    agg_k<<<AGG_BLOCKS, 256>>>(buf1, buf2);
    // v = tanh(m @ W_hyp + b_hyp)      -> buf0
    sgemm_k<2><<<gBig, blk>>>(buf2, W_hyp, b_hyp, buf0, ROWS, 512, 512, 512);

    // attention layer 0: NF -> buf1
    run_attention(buf0, buf1, aWq, aWk, aWv, aWo, gamma, beta, buf2, buf3, buf4);

    // m = agg(NF) -> buf2 ; v = tanh(m @ Wquat + b_quat) -> buf0
    agg_k<<<AGG_BLOCKS, 256>>>(buf1, buf2);
    sgemm_k<2><<<gBig, blk>>>(buf2, wq, b_quat, buf0, ROWS, 512, 512, 512);

    // attention layer 1
    run_attention(buf0, buf1, aWq + 262144, aWk + 262144, aWv + 262144, aWo + 262144,
                  gamma + 512, beta + 512, buf2, buf3, buf4);

    // m = agg(NF) -> buf2 ; v = tanh(m @ Wwav + b_wav) -> buf0
    agg_k<<<AGG_BLOCKS, 256>>>(buf1, buf2);
    sgemm_k<2><<<gBig, blk>>>(buf2, ww, b_wav, buf0, ROWS, 512, 512, 512);

    // attention layer 2
    run_attention(buf0, buf1, aWq + 2 * 262144, aWk + 2 * 262144, aWv + 2 * 262144, aWo + 2 * 262144,
                  gamma + 1024, beta + 1024, buf2, buf3, buf4);

    // out = NF[:, 8, :] @ W_out + b_out   (A rows strided by 9*512)
    sgemm_k<3><<<dim3(1, 128), blk>>>(buf1 + 8 * H_SZ, W_out, b_out, out,
                                      B_SZ, 128, 512, NODES * H_SZ);
}

// round 4
// speedup vs baseline: 2.4245x; 2.4245x over previous
#include <cuda_runtime.h>
#include <cuda_fp16.h>
#include <math.h>
#include <stdint.h>

#define B_SZ   16384
#define H_SZ   512
#define NODES  9
#define ROWS   (B_SZ * NODES)         // 147456
#define BH     (ROWS * H_SZ)          // 75497472

// ---------------- scratch (device globals; no allocation) ----------------
// activation hi/lo half pairs
__device__ __half g_mh[BH], g_ml[BH];     // "m" / p buffer
__device__ __half g_ah[BH], g_al[BH];     // "v" activation
__device__ __half g_nh[BH], g_nl[BH];     // NF
__device__ __half g_ch[BH], g_cl[BH];     // attention ctx
__device__ __half g_xh[B_SZ * H_SZ], g_xl[B_SZ * H_SZ];
// fp32 intermediates (Q, K, V / attn-out)
__device__ float g_f0[BH], g_f1[BH], g_f2[BH];

// transposed weights [N,K] K-major, K=512, hi/lo half pairs
#define OFF_WIN   0                    // 4608*512
#define OFF_WDR   2359296
#define OFF_WHYP  2621440
#define OFF_QUAT  2883584
#define OFF_WAV   3145728
#define OFF_ATT   3407872              // 12 * 262144
#define OFF_WOUT  6553600              // 128*512
#define WTS_TOTAL 6619136
__device__ __half g_wh[WTS_TOTAL], g_wl[WTS_TOTAL];

// ============================================================================
// helpers
// ============================================================================
__device__ __forceinline__ uint32_t smem_u32(const void* p) {
    uint32_t a;
    asm("{ .reg .u64 t; cvta.to.shared.u64 t, %1; cvt.u32.u64 %0, t; }" : "=r"(a) : "l"(p));
    return a;
}
__device__ __forceinline__ void cp_async16(uint32_t dst, const void* src) {
    asm volatile("cp.async.cg.shared.global [%0], [%1], 16;" :: "r"(dst), "l"(src) : "memory");
}
__device__ __forceinline__ void cp_commit() {
    asm volatile("cp.async.commit_group;" ::: "memory");
}
__device__ __forceinline__ void cp_wait2() {
    asm volatile("cp.async.wait_group 2;" ::: "memory");
}
__device__ __forceinline__ void ldm_x4(uint32_t addr, uint32_t& r0, uint32_t& r1,
                                       uint32_t& r2, uint32_t& r3) {
    asm volatile("ldmatrix.sync.aligned.m8n8.x4.shared.b16 {%0,%1,%2,%3}, [%4];"
                 : "=r"(r0), "=r"(r1), "=r"(r2), "=r"(r3) : "r"(addr));
}
__device__ __forceinline__ void mma_f16(float* c, const uint32_t* a, const uint32_t* b) {
    asm volatile(
        "mma.sync.aligned.m16n8k16.row.col.f32.f16.f16.f32 "
        "{%0,%1,%2,%3}, {%4,%5,%6,%7}, {%8,%9}, {%0,%1,%2,%3};"
        : "+f"(c[0]), "+f"(c[1]), "+f"(c[2]), "+f"(c[3])
        : "r"(a[0]), "r"(a[1]), "r"(a[2]), "r"(a[3]), "r"(b[0]), "r"(b[1]));
}
__device__ __forceinline__ void split2(float d0, float d1, __half2& h, __half2& l) {
    __half h0 = __float2half_rn(d0), h1 = __float2half_rn(d1);
    h = __halves2half2(h0, h1);
    l = __floats2half2_rn(d0 - __half2float(h0), d1 - __half2float(h1));
}

// ============================================================================
// fp16x3 GEMM: C[M,N] = A[M,512] @ Bt[N,512]^T  (A = Ah+Al, B = Bh+Bl)
// EPI: 0 fp32 C out; 1 bias+lrelu -> HL; 2 bias+tanh -> HL; 3 bias -> fp32
// BM=BN=128, BK=64(halves)=128B rows, 3-stage cp.async, 256 threads
// ============================================================================
#define ST 16384
#define TG_SMEM (12 * ST + 1024)

template<int EPI>
__global__ __launch_bounds__(256, 1)
void hgemm3(const __half* __restrict__ Ah, const __half* __restrict__ Al,
            const __half* __restrict__ Bh, const __half* __restrict__ Bl,
            const float* __restrict__ bias, float* __restrict__ C,
            __half* __restrict__ Ch, __half* __restrict__ Cl,
            int N, int lda)
{
    extern __shared__ char smraw[];
    const uint32_t base = (smem_u32(smraw) + 1023) & ~1023u;
    const uint32_t sAh = base;
    const uint32_t sAl = base + 3 * ST;
    const uint32_t sBh = base + 6 * ST;
    const uint32_t sBl = base + 9 * ST;

    const int tid    = threadIdx.x;
    const int lane   = tid & 31;
    const int wid    = tid >> 5;
    const int warp_m = wid >> 2;        // 0..1
    const int warp_n = wid & 3;         // 0..3
    const int row0   = blockIdx.y * 128;
    const int col0   = blockIdx.x * 128;

    // cp.async mapping: chunk c = tid + i*256 -> row = c>>3, q = c&7
    const int lm = tid >> 3;
    const int lq = tid & 7;

    // ldmatrix address components (validated mapping)
    const int mat = lane >> 3;
    const int mr  = lane & 7;
    int rbA[4], s7A[4];
    #pragma unroll
    for (int mf = 0; mf < 4; ++mf) {
        int m = warp_m * 64 + mf * 16 + (mat & 1) * 8 + mr;
        rbA[mf] = m * 128; s7A[mf] = m & 7;
    }
    const int qaA = mat >> 1;
    int rbB[2], s7B[2];
    #pragma unroll
    for (int p = 0; p < 2; ++p) {
        int n = warp_n * 32 + (2 * p + (mat >> 1)) * 8 + mr;
        rbB[p] = n * 128; s7B[p] = n & 7;
    }
    const int qaB = mat & 1;

    float acc[4][4][4];
    #pragma unroll
    for (int i = 0; i < 4; ++i)
        #pragma unroll
        for (int j = 0; j < 4; ++j)
            #pragma unroll
            for (int k = 0; k < 4; ++k) acc[i][j][k] = 0.f;

    // prologue: stages 0, 1
    #pragma unroll
    for (int st = 0; st < 2; ++st) {
        #pragma unroll
        for (int i = 0; i < 4; ++i) {
            const int row = lm + i * 32;
            const uint32_t d = st * ST + row * 128 + (((lq ^ (row & 7)) << 4));
            const size_t oa = (size_t)(row0 + row) * lda + st * 64 + lq * 8;
            const size_t ob = (size_t)(col0 + row) * 512 + st * 64 + lq * 8;
            cp_async16(sAh + d, Ah + oa);
            cp_async16(sAl + d, Al + oa);
            cp_async16(sBh + d, Bh + ob);
            cp_async16(sBl + d, Bl + ob);
        }
        cp_commit();
    }

    #pragma unroll 1
    for (int t = 0; t < 8; ++t) {
        if (t + 2 < 8) {
            const int slot = (t + 2) % 3;
            #pragma unroll
            for (int i = 0; i < 4; ++i) {
                const int row = lm + i * 32;
                const uint32_t d = slot * ST + row * 128 + (((lq ^ (row & 7)) << 4));
                const size_t oa = (size_t)(row0 + row) * lda + (t + 2) * 64 + lq * 8;
                const size_t ob = (size_t)(col0 + row) * 512 + (t + 2) * 64 + lq * 8;
                cp_async16(sAh + d, Ah + oa);
                cp_async16(sAl + d, Al + oa);
                cp_async16(sBh + d, Bh + ob);
                cp_async16(sBl + d, Bl + ob);
            }
        }
        cp_commit();
        cp_wait2();
        __syncthreads();

        const uint32_t pAh = sAh + (t % 3) * ST;
        const uint32_t pAl = sAl + (t % 3) * ST;
        const uint32_t pBh = sBh + (t % 3) * ST;
        const uint32_t pBl = sBl + (t % 3) * ST;

        #pragma unroll
        for (int ks = 0; ks < 4; ++ks) {
            uint32_t ah[4][4], al[4][4], bh[4][2], bl[4][2];
            #pragma unroll
            for (int mf = 0; mf < 4; ++mf) {
                const uint32_t off = rbA[mf] + (((2 * ks + qaA) ^ s7A[mf]) << 4);
                ldm_x4(pAh + off, ah[mf][0], ah[mf][1], ah[mf][2], ah[mf][3]);
                ldm_x4(pAl + off, al[mf][0], al[mf][1], al[mf][2], al[mf][3]);
            }
            #pragma unroll
            for (int p = 0; p < 2; ++p) {
                const uint32_t off = rbB[p] + (((2 * ks + qaB) ^ s7B[p]) << 4);
                ldm_x4(pBh + off, bh[2*p][0], bh[2*p][1], bh[2*p+1][0], bh[2*p+1][1]);
                ldm_x4(pBl + off, bl[2*p][0], bl[2*p][1], bl[2*p+1][0], bl[2*p+1][1]);
            }
            #pragma unroll
            for (int mf = 0; mf < 4; ++mf)
                #pragma unroll
                for (int nf = 0; nf < 4; ++nf) {
                    mma_f16(acc[mf][nf], ah[mf], bh[nf]);
                    mma_f16(acc[mf][nf], ah[mf], bl[nf]);
                    mma_f16(acc[mf][nf], al[mf], bh[nf]);
                }
        }
        __syncthreads();
    }

    // ---- epilogue
    const int g  = lane >> 2;
    const int t4 = lane & 3;
    #pragma unroll
    for (int mf = 0; mf < 4; ++mf) {
        #pragma unroll
        for (int nf = 0; nf < 4; ++nf) {
            const int r1 = row0 + warp_m * 64 + mf * 16 + g;
            const int cc = col0 + warp_n * 32 + nf * 8 + t4 * 2;
            float d[4] = {acc[mf][nf][0], acc[mf][nf][1], acc[mf][nf][2], acc[mf][nf][3]};
            if (EPI != 0) {
                float b0 = __ldg(bias + cc), b1 = __ldg(bias + cc + 1);
                d[0] += b0; d[1] += b1; d[2] += b0; d[3] += b1;
                #pragma unroll
                for (int i = 0; i < 4; ++i) {
                    if (EPI == 1)      d[i] = d[i] > 0.f ? d[i] : 0.01f * d[i];
                    else if (EPI == 2) d[i] = tanhf(d[i]);
                }
            }
            if (EPI == 0 || EPI == 3) {
                *(float2*)(C + (size_t)r1 * N + cc)       = make_float2(d[0], d[1]);
                *(float2*)(C + (size_t)(r1 + 8) * N + cc) = make_float2(d[2], d[3]);
            } else {
                __half2 h, l;
                split2(d[0], d[1], h, l);
                *(__half2*)(Ch + (size_t)r1 * N + cc) = h;
                *(__half2*)(Cl + (size_t)r1 * N + cc) = l;
                split2(d[2], d[3], h, l);
                *(__half2*)(Ch + (size_t)(r1 + 8) * N + cc) = h;
                *(__half2*)(Cl + (size_t)(r1 + 8) * N + cc) = l;
            }
        }
    }
}

// ============================================================================
// weight prep: transpose [K,N] -> [N,K] and split hi/lo
// ============================================================================
__global__ void transpose_split(const float* __restrict__ in, __half* __restrict__ oh,
                                __half* __restrict__ ol, int K, int N)
{
    __shared__ float s[32][33];
    const int bx = blockIdx.x * 32, by = blockIdx.y * 32;
    const int tx = threadIdx.x, ty = threadIdx.y;
    #pragma unroll
    for (int i = 0; i < 32; i += 8)
        s[ty + i][tx] = in[(size_t)(by + ty + i) * N + bx + tx];
    __syncthreads();
    #pragma unroll
    for (int i = 0; i < 32; i += 8) {
        float v = s[tx][ty + i];
        __half h = __float2half_rn(v);
        size_t o = (size_t)(bx + ty + i) * K + by + tx;
        oh[o] = h;
        ol[o] = __float2half_rn(v - __half2float(h));
    }
}

__constant__ int   c_which[16] = {0,1,2,3, 1,0,3,2, 2,3,0,1, 3,2,1,0};
__constant__ float c_sign [16] = {1.f,-1.f,-1.f,-1.f,
                                  1.f, 1.f, 1.f,-1.f,
                                  1.f,-1.f, 1.f, 1.f,
                                  1.f, 1.f,-1.f, 1.f};

__global__ void build_quat_t(const float* __restrict__ Wr, const float* __restrict__ Wi,
                             const float* __restrict__ Wj, const float* __restrict__ Wk,
                             __half* __restrict__ oh, __half* __restrict__ ol)
{
    int idx = blockIdx.x * 256 + threadIdx.x;
    int n = idx >> 9, k = idx & 511;
    int co = n >> 7, ho = n & 127;
    int ci = k >> 7, hi = k & 127;
    const float* mats[4] = {Wr, Wi, Wj, Wk};
    int sel = co * 4 + ci;
    float v = c_sign[sel] * mats[c_which[sel]][hi * 128 + ho];
    __half h = __float2half_rn(v);
    oh[idx] = h; ol[idx] = __float2half_rn(v - __half2float(h));
}

__global__ void build_wav_t(const float* __restrict__ Wl_, const float* __restrict__ Wh_,
                            __half* __restrict__ oh, __half* __restrict__ ol)
{
    int idx = blockIdx.x * 256 + threadIdx.x;
    int n = idx >> 9, k = idx & 511;
    int ho = n >> 1, po = n & 1;
    int hi = k >> 1, pi = k & 1;
    float wl = Wl_[hi * 256 + ho];
    float wh = Wh_[hi * 256 + ho];
    float v = (pi == po) ? 0.5f * (wl + wh) : 0.5f * (wl - wh);
    __half h = __float2half_rn(v);
    oh[idx] = h; ol[idx] = __float2half_rn(v - __half2float(h));
}

__global__ void split_copy(const float4* __restrict__ in, __half* __restrict__ H,
                           __half* __restrict__ L, int n4)
{
    int i = blockIdx.x * 256 + threadIdx.x;
    if (i >= n4) return;
    float4 v = in[i];
    __half2 h, l;
    split2(v.x, v.y, h, l);
    ((__half2*)H)[2*i]   = h; ((__half2*)L)[2*i]   = l;
    split2(v.z, v.w, h, l);
    ((__half2*)H)[2*i+1] = h; ((__half2*)L)[2*i+1] = l;
}

// ============================================================================
// elementwise kernels on hi/lo pairs
// ============================================================================
__global__ void agg_hl(const __half2* __restrict__ ih, const __half2* __restrict__ il,
                       __half2* __restrict__ oh, __half2* __restrict__ ol)
{
    int idx = blockIdx.x * 256 + threadIdx.x;          // over B*9*256 half2
    const int TOT = B_SZ * NODES * 256;
    if (idx >= TOT) return;
    int h2 = idx & 255;
    int rn = (idx >> 8) % NODES;
    int b  = idx / (NODES * 256);
    size_t p = (size_t)(b * NODES + rn) * 256 + h2;
    __half2 xh = ih[p], xl = il[p];
    if (rn == 8) { oh[idx] = xh; ol[idx] = xl; return; }
    int src = (rn & 1) ? (rn >> 1) : (rn >> 1) + 4;
    size_t q = (size_t)(b * NODES + src) * 256 + h2;
    float2 fa = __half22float2(xh), fal = __half22float2(xl);
    float2 fc = __half22float2(ih[q]), fcl = __half22float2(il[q]);
    float v0 = 0.5f * ((fa.x + fal.x) + (fc.x + fcl.x));
    float v1 = 0.5f * ((fa.y + fal.y) + (fc.y + fcl.y));
    __half2 h, l;
    split2(v0, v1, h, l);
    oh[idx] = h; ol[idx] = l;
}

__global__ __launch_bounds__(256)
void attn_core(const float* __restrict__ Q, const float* __restrict__ Kk,
               const float* __restrict__ Vv,
               __half* __restrict__ Ch, __half* __restrict__ Cl)
{
    __shared__ float sK[NODES * H_SZ];
    __shared__ float sV[NODES * H_SZ];
    __shared__ float sS[96];
    const int b   = blockIdx.x;
    const int tid = threadIdx.x;
    const size_t base = (size_t)b * NODES * H_SZ;

    const float4* K4 = (const float4*)(Kk + base);
    const float4* V4 = (const float4*)(Vv + base);
    for (int i = tid; i < NODES * H_SZ / 4; i += 256) {
        ((float4*)sK)[i] = K4[i];
        ((float4*)sV)[i] = V4[i];
    }
    __syncthreads();

    const float scale = 0.044194173824159216f;   // 1/sqrt(512)
    const int warp = tid >> 5, lane = tid & 31;
    for (int p = warp; p < 81; p += 8) {
        int q = p / 9, kk = p % 9;
        const float* Qr = Q + base + (size_t)q * H_SZ;
        float s = 0.f;
        #pragma unroll 4
        for (int h = lane; h < H_SZ; h += 32) s += Qr[h] * sK[kk * H_SZ + h];
        #pragma unroll
        for (int o = 16; o; o >>= 1) s += __shfl_down_sync(0xffffffffu, s, o);
        if (lane == 0) sS[q * 9 + kk] = s * scale;
    }
    __syncthreads();

    if (tid < 9) {
        float mx = -1e30f;
        #pragma unroll
        for (int k = 0; k < 9; ++k) mx = fmaxf(mx, sS[tid * 9 + k]);
        float sum = 0.f;
        #pragma unroll
        for (int k = 0; k < 9; ++k) { float e = expf(sS[tid * 9 + k] - mx); sS[tid * 9 + k] = e; sum += e; }
        float inv = 1.f / sum;
        #pragma unroll
        for (int k = 0; k < 9; ++k) sS[tid * 9 + k] *= inv;
    }
    __syncthreads();

    for (int q = 0; q < 9; ++q) {
        float a[9];
        #pragma unroll
        for (int k = 0; k < 9; ++k) a[k] = sS[q * 9 + k];
        for (int h = tid * 2; h < H_SZ; h += 512) {
            float a0 = 0.f, a1 = 0.f;
            #pragma unroll
            for (int k = 0; k < 9; ++k) {
                a0 = fmaf(a[k], sV[k * H_SZ + h],     a0);
                a1 = fmaf(a[k], sV[k * H_SZ + h + 1], a1);
            }
            __half2 hh, ll;
            split2(a0, a1, hh, ll);
            *(__half2*)(Ch + base + (size_t)q * H_SZ + h) = hh;
            *(__half2*)(Cl + base + (size_t)q * H_SZ + h) = ll;
        }
    }
}

__global__ __launch_bounds__(256)
void drnorm_res(const float* __restrict__ A,
                const __half* __restrict__ Vh, const __half* __restrict__ Vl,
                const float* __restrict__ gamma, const float* __restrict__ beta,
                __half* __restrict__ Nh, __half* __restrict__ Nl)
{
    __shared__ float red[16];
    __shared__ float s_mu, s_inv;
    const int row = blockIdx.x;
    const int t = threadIdx.x;
    const size_t o0 = (size_t)row * H_SZ;
    float v1 = A[o0 + t], v2 = A[o0 + t + 256];
    float s = v1 + v2, sq = v1 * v1 + v2 * v2;
    #pragma unroll
    for (int o = 16; o; o >>= 1) {
        s  += __shfl_down_sync(0xffffffffu, s, o);
        sq += __shfl_down_sync(0xffffffffu, sq, o);
    }
    int warp = t >> 5, lane = t & 31;
    if (lane == 0) { red[warp] = s; red[warp + 8] = sq; }
    __syncthreads();
    if (t == 0) {
        float S = 0.f, SQ = 0.f;
        #pragma unroll
        for (int w = 0; w < 8; ++w) { S += red[w]; SQ += red[w + 8]; }
        float mu = S * (1.f / 512.f);
        float var = SQ * (1.f / 512.f) - mu * mu;
        s_mu = mu; s_inv = rsqrtf(var + 1e-5f);
    }
    __syncthreads();
    float mu = s_mu, inv = s_inv;
    #pragma unroll
    for (int half = 0; half < 2; ++half) {
        int i = t + half * 256;
        float av = half ? v2 : v1;
        float resid = __half2float(Vh[o0 + i]) + __half2float(Vl[o0 + i]);
        float d = resid + gamma[i] * (av - mu) * inv + beta[i];
        __half h = __float2half_rn(d);
        Nh[o0 + i] = h;
        Nl[o0 + i] = __float2half_rn(d - __half2float(h));
    }
}

// ============================================================================
// host orchestration
// ============================================================================
template<int EPI>
static void launch_hg(const __half* Ah, const __half* Al, const __half* Bh, const __half* Bl,
                      const float* bias, float* C, __half* Ch, __half* Cl,
                      int M, int N, int lda)
{
    cudaFuncSetAttribute(hgemm3<EPI>, cudaFuncAttributeMaxDynamicSharedMemorySize, TG_SMEM);
    dim3 grid(N / 128, M / 128);
    hgemm3<EPI><<<grid, 256, TG_SMEM>>>(Ah, Al, Bh, Bl, bias, C, Ch, Cl, N, lda);
}

struct Ptrs {
    __half *mh, *ml, *ah, *al, *nh, *nl, *ch, *cl, *xh, *xl, *wh, *wl;
    float *f0, *f1, *f2;
};

static void run_attention(const Ptrs& P, int layer, const float* gamma, const float* beta)
{
    const __half* Wqh = P.wh + OFF_ATT + (size_t)(layer * 4 + 0) * 262144;
    const __half* Wql = P.wl + OFF_ATT + (size_t)(layer * 4 + 0) * 262144;
    const __half* Wkh = P.wh + OFF_ATT + (size_t)(layer * 4 + 1) * 262144;
    const __half* Wkl = P.wl + OFF_ATT + (size_t)(layer * 4 + 1) * 262144;
    const __half* Wvh = P.wh + OFF_ATT + (size_t)(layer * 4 + 2) * 262144;
    const __half* Wvl = P.wl + OFF_ATT + (size_t)(layer * 4 + 2) * 262144;
    const __half* Woh = P.wh + OFF_ATT + (size_t)(layer * 4 + 3) * 262144;
    const __half* Wol = P.wl + OFF_ATT + (size_t)(layer * 4 + 3) * 262144;
    launch_hg<0>(P.ah, P.al, Wqh, Wql, nullptr, P.f0, nullptr, nullptr, ROWS, 512, 512);
    launch_hg<0>(P.ah, P.al, Wkh, Wkl, nullptr, P.f1, nullptr, nullptr, ROWS, 512, 512);
    launch_hg<0>(P.ah, P.al, Wvh, Wvl, nullptr, P.f2, nullptr, nullptr, ROWS, 512, 512);
    attn_core<<<B_SZ, 256>>>(P.f0, P.f1, P.f2, P.ch, P.cl);
    launch_hg<0>(P.ch, P.cl, Woh, Wol, nullptr, P.f1, nullptr, nullptr, ROWS, 512, 512);
    drnorm_res<<<ROWS, 256>>>(P.f1, P.ah, P.al, gamma, beta, P.nh, P.nl);
}

extern "C" void kernel_launch(void* const* d_in, const int* in_sizes, int n_in,
                              void* d_out, int out_size)
{
    const float* x      = (const float*)d_in[0];
    const float* W_in   = (const float*)d_in[1];
    const float* b_in   = (const float*)d_in[2];
    const float* W_dr   = (const float*)d_in[3];
    const float* b_dr   = (const float*)d_in[4];
    const float* W_hyp  = (const float*)d_in[5];
    const float* b_hyp  = (const float*)d_in[6];
    const float* Wq_r   = (const float*)d_in[7];
    const float* Wq_i   = (const float*)d_in[8];
    const float* Wq_j   = (const float*)d_in[9];
    const float* Wq_k   = (const float*)d_in[10];
    const float* b_quat = (const float*)d_in[11];
    const float* W_low  = (const float*)d_in[12];
    const float* W_high = (const float*)d_in[13];
    const float* b_wav  = (const float*)d_in[14];
    const float* aWq    = (const float*)d_in[15];
    const float* aWk    = (const float*)d_in[16];
    const float* aWv    = (const float*)d_in[17];
    const float* aWo    = (const float*)d_in[18];
    const float* gamma  = (const float*)d_in[19];
    const float* beta   = (const float*)d_in[20];
    const float* W_out  = (const float*)d_in[21];
    const float* b_out  = (const float*)d_in[22];
    float* out = (float*)d_out;

    Ptrs P;
    cudaGetSymbolAddress((void**)&P.mh, g_mh); cudaGetSymbolAddress((void**)&P.ml, g_ml);
    cudaGetSymbolAddress((void**)&P.ah, g_ah); cudaGetSymbolAddress((void**)&P.al, g_al);
    cudaGetSymbolAddress((void**)&P.nh, g_nh); cudaGetSymbolAddress((void**)&P.nl, g_nl);
    cudaGetSymbolAddress((void**)&P.ch, g_ch); cudaGetSymbolAddress((void**)&P.cl, g_cl);
    cudaGetSymbolAddress((void**)&P.xh, g_xh); cudaGetSymbolAddress((void**)&P.xl, g_xl);
    cudaGetSymbolAddress((void**)&P.wh, g_wh); cudaGetSymbolAddress((void**)&P.wl, g_wl);
    cudaGetSymbolAddress((void**)&P.f0, g_f0); cudaGetSymbolAddress((void**)&P.f1, g_f1);
    cudaGetSymbolAddress((void**)&P.f2, g_f2);

    // ---- weight prep ----
    dim3 tb(32, 8);
    transpose_split<<<dim3(4608/32, 512/32), tb>>>(W_in,  P.wh + OFF_WIN,  P.wl + OFF_WIN,  512, 4608);
    transpose_split<<<dim3(16, 16), tb>>>(W_dr,  P.wh + OFF_WDR,  P.wl + OFF_WDR,  512, 512);
    transpose_split<<<dim3(16, 16), tb>>>(W_hyp, P.wh + OFF_WHYP, P.wl + OFF_WHYP, 512, 512);
    build_quat_t<<<1024, 256>>>(Wq_r, Wq_i, Wq_j, Wq_k, P.wh + OFF_QUAT, P.wl + OFF_QUAT);
    build_wav_t <<<1024, 256>>>(W_low, W_high, P.wh + OFF_WAV, P.wl + OFF_WAV);
    for (int l = 0; l < 3; ++l) {
        transpose_split<<<dim3(16,16), tb>>>(aWq + (size_t)l*262144, P.wh + OFF_ATT + (size_t)(l*4+0)*262144, P.wl + OFF_ATT + (size_t)(l*4+0)*262144, 512, 512);
        transpose_split<<<dim3(16,16), tb>>>(aWk + (size_t)l*262144, P.wh + OFF_ATT + (size_t)(l*4+1)*262144, P.wl + OFF_ATT + (size_t)(l*4+1)*262144, 512, 512);
        transpose_split<<<dim3(16,16), tb>>>(aWv + (size_t)l*262144, P.wh + OFF_ATT + (size_t)(l*4+2)*262144, P.wl + OFF_ATT + (size_t)(l*4+2)*262144, 512, 512);
        transpose_split<<<dim3(16,16), tb>>>(aWo + (size_t)l*262144, P.wh + OFF_ATT + (size_t)(l*4+3)*262144, P.wl + OFF_ATT + (size_t)(l*4+3)*262144, 512, 512);
    }
    transpose_split<<<dim3(4, 16), tb>>>(W_out, P.wh + OFF_WOUT, P.wl + OFF_WOUT, 512, 128);
    split_copy<<<(B_SZ * H_SZ / 4 + 255) / 256, 256>>>((const float4*)x, P.xh, P.xl, B_SZ * H_SZ / 4);

    const int AGG_BLOCKS = (B_SZ * NODES * 256 + 255) / 256;

    // p = leakyrelu(x @ W_in + b_in) -> m pair (viewed ROWS x 512)
    launch_hg<1>(P.xh, P.xl, P.wh + OFF_WIN, P.wl + OFF_WIN, b_in, nullptr, P.mh, P.ml, B_SZ, 4608, 512);
    // nf = tanh(p @ W_dr + b_dr) -> n pair
    launch_hg<2>(P.mh, P.ml, P.wh + OFF_WDR, P.wl + OFF_WDR, b_dr, nullptr, P.nh, P.nl, ROWS, 512, 512);
    agg_hl<<<AGG_BLOCKS, 256>>>((const __half2*)P.nh, (const __half2*)P.nl, (__half2*)P.mh, (__half2*)P.ml);
    launch_hg<2>(P.mh, P.ml, P.wh + OFF_WHYP, P.wl + OFF_WHYP, b_hyp, nullptr, P.ah, P.al, ROWS, 512, 512);

    run_attention(P, 0, gamma, beta);

    agg_hl<<<AGG_BLOCKS, 256>>>((const __half2*)P.nh, (const __half2*)P.nl, (__half2*)P.mh, (__half2*)P.ml);
    launch_hg<2>(P.mh, P.ml, P.wh + OFF_QUAT, P.wl + OFF_QUAT, b_quat, nullptr, P.ah, P.al, ROWS, 512, 512);

    run_attention(P, 1, gamma + 512, beta + 512);

    agg_hl<<<AGG_BLOCKS, 256>>>((const __half2*)P.nh, (const __half2*)P.nl, (__half2*)P.mh, (__half2*)P.ml);
    launch_hg<2>(P.mh, P.ml, P.wh + OFF_WAV, P.wl + OFF_WAV, b_wav, nullptr, P.ah, P.al, ROWS, 512, 512);

    run_attention(P, 2, gamma + 1024, beta + 1024);

    // out = NF[:, 8, :] @ W_out + b_out
    launch_hg<3>(P.nh + 8 * H_SZ, P.nl + 8 * H_SZ, P.wh + OFF_WOUT, P.wl + OFF_WOUT,
                 b_out, out, nullptr, nullptr, B_SZ, 128, NODES * H_SZ);
}